// round 3
// baseline (speedup 1.0000x reference)
#include <cuda_runtime.h>
#include <math.h>

#define NCOLS  16384
#define NT     256
#define V4     (NCOLS / 4 / NT)     // 16 float4 per thread
#define KSEL   256
#define CAP    4096
#define NW     (NT / 32)

__global__ __launch_bounds__(NT, 6)
void entmax_topk_kernel(const float* __restrict__ logits,
                        float* __restrict__ out_w,
                        float* __restrict__ out_cnt)
{
    __shared__ float cand[CAP];
    __shared__ float s_f[NW];
    __shared__ int   s_i[NW];
    __shared__ int   s_cn;

    const int tid  = threadIdx.x;
    const int lane = tid & 31;
    const int wid  = tid >> 5;
    const int row  = blockIdx.x;

    const float4* src = reinterpret_cast<const float4*>(logits) + (size_t)row * (NCOLS / 4);
    float4*       dst = reinterpret_cast<float4*>(out_w)        + (size_t)row * (NCOLS / 4);

    // ---------- Pass A: single DRAM read; per-thread top-4 (z = 0.5*x) ----------
    float t0 = -INFINITY, t1 = -INFINITY, t2 = -INFINITY, t3 = -INFINITY;
    #pragma unroll
    for (int j = 0; j < V4; ++j) {
        float4 v = src[tid + j * NT];
        float zx = 0.5f * v.x, zy = 0.5f * v.y, zz = 0.5f * v.z, zw = 0.5f * v.w;
        // sort4 descending (compare-exchange network)
        float a0 = fmaxf(zx, zy), b0 = fminf(zx, zy);
        float a1 = fmaxf(zz, zw), b1 = fminf(zz, zw);
        float s0 = fmaxf(a0, a1), m0 = fminf(a0, a1);
        float s3 = fminf(b0, b1), m1 = fmaxf(b0, b1);
        float s1 = fmaxf(m0, m1), s2 = fminf(m0, m1);
        // merge two sorted-4s, keep top-4:  c_i = max(a_i, b_i, max_{j+k=i-1} min(a_j,b_k))
        float n0 = fmaxf(t0, s0);
        float n1 = fmaxf(fmaxf(t1, s1), fminf(t0, s0));
        float n2 = fmaxf(fmaxf(t2, s2), fmaxf(fminf(t0, s1), fminf(t1, s0)));
        float n3 = fmaxf(fmaxf(t3, s3),
                   fmaxf(fminf(t0, s2), fmaxf(fminf(t1, s1), fminf(t2, s0))));
        t0 = n0; t1 = n1; t2 = n2; t3 = n3;
    }

    // block max (zmax = max of t0)
    float lmax = t0;
    #pragma unroll
    for (int o = 16; o; o >>= 1) lmax = fmaxf(lmax, __shfl_xor_sync(0xffffffffu, lmax, o));
    if (lane == 0) s_f[wid] = lmax;
    __syncthreads();
    if (wid == 0) {
        float m = (lane < NW) ? s_f[lane] : -INFINITY;
        #pragma unroll
        for (int o = 16; o; o >>= 1) m = fmaxf(m, __shfl_xor_sync(0xffffffffu, m, o));
        if (lane == 0) s_f[0] = m;
    }
    __syncthreads();
    const float zmax   = s_f[0];
    const float cutoff = zmax - 1.0f;          // rigorous lower bound on tau
    __syncthreads();                            // guard s_f reuse

    // ---------- candidate count (top-4 stash; rare fallback if t3 > cutoff) ----------
    const bool fb = (t3 > cutoff);              // thread may own >4 candidates
    int lc;
    if (!fb) {
        lc = (t0 > cutoff) + (t1 > cutoff) + (t2 > cutoff);
    } else {
        lc = 0;
        #pragma unroll
        for (int j = 0; j < V4; ++j) {
            float4 v = src[tid + j * NT];       // L2 hit
            lc += (0.5f * v.x > cutoff) + (0.5f * v.y > cutoff)
                + (0.5f * v.z > cutoff) + (0.5f * v.w > cutoff);
        }
    }
    // deterministic exclusive scan
    int inc = lc;
    #pragma unroll
    for (int o = 1; o < 32; o <<= 1) {
        int t = __shfl_up_sync(0xffffffffu, inc, o);
        if (lane >= o) inc += t;
    }
    if (lane == 31) s_i[wid] = inc;
    __syncthreads();
    if (wid == 0) {
        int v = (lane < NW) ? s_i[lane] : 0;
        int winc = v;
        #pragma unroll
        for (int o = 1; o < NW; o <<= 1) {
            int u = __shfl_up_sync(0xffffffffu, winc, o);
            if (lane >= o) winc += u;
        }
        if (lane < NW) s_i[lane] = winc - v;    // exclusive warp bases
        if (lane == NW - 1) s_cn = winc;
    }
    __syncthreads();
    const int  cn      = s_cn;
    const bool useSmem = (cn <= CAP);
    if (useSmem && lc > 0) {
        int o = s_i[wid] + (inc - lc);
        if (!fb) {
            if (t0 > cutoff) cand[o++] = t0;
            if (t1 > cutoff) cand[o++] = t1;
            if (t2 > cutoff) cand[o++] = t2;
        } else {
            #pragma unroll
            for (int j = 0; j < V4; ++j) {
                float4 v = src[tid + j * NT];   // L1/L2 hit
                float z;
                z = 0.5f * v.x; if (z > cutoff) cand[o++] = z;
                z = 0.5f * v.y; if (z > cutoff) cand[o++] = z;
                z = 0.5f * v.z; if (z > cutoff) cand[o++] = z;
                z = 0.5f * v.w; if (z > cutoff) cand[o++] = z;
            }
        }
    }
    __syncthreads();

    // ---------- tau solve: ALL warps redundantly (identical ops -> identical result) ----------
    float tau = cutoff, th, inv;
    int useGe = 0;
    if (useSmem && cn <= 256) {
        // register-cached fast path (typical cn ~ 175)
        float rv[8];
        #pragma unroll
        for (int r = 0; r < 8; ++r) {
            int idx = r * 32 + lane;
            rv[r] = (idx < cn) ? cand[idx] : -1e30f;
        }
        float gfin = 0.f;
        for (int it = 0; it < 24; ++it) {
            float g = 0.f, gp = 0.f;
            #pragma unroll
            for (int r = 0; r < 8; ++r) {
                float d = rv[r] - tau;
                if (d > 0.f) { g = fmaf(d, d, g); gp += d; }
            }
            #pragma unroll
            for (int o = 16; o; o >>= 1) {
                g  += __shfl_xor_sync(0xffffffffu, g,  o);
                gp += __shfl_xor_sync(0xffffffffu, gp, o);
            }
            gfin = g;
            g -= 1.0f;
            if (gp <= 0.f) break;
            float step = g / (2.0f * gp);
            tau += step;
            if (step < 1e-7f) break;
        }
        int S = 0;
        #pragma unroll
        for (int r = 0; r < 8; ++r) S += (rv[r] > tau) ? 1 : 0;
        #pragma unroll
        for (int o = 16; o; o >>= 1) S += __shfl_xor_sync(0xffffffffu, S, o);

        th = tau;
        float ssum = gfin;                       // sum (z-tau)_+^2 at final tau
        if (S > KSEL) {                          // rare: K-th largest z via bisection
            useGe = 1;
            float lo = tau, hi = zmax;
            for (int it = 0; it < 48; ++it) {
                float mid = 0.5f * (lo + hi);
                int c = 0;
                #pragma unroll
                for (int r = 0; r < 8; ++r) c += (rv[r] >= mid) ? 1 : 0;
                #pragma unroll
                for (int o = 16; o; o >>= 1) c += __shfl_xor_sync(0xffffffffu, c, o);
                if (c >= KSEL) lo = mid; else hi = mid;
            }
            th = lo;
            ssum = 0.f;
            #pragma unroll
            for (int r = 0; r < 8; ++r) {
                float z = rv[r], d = z - tau;
                if (z >= th && d > 0.f) ssum = fmaf(d, d, ssum);
            }
            #pragma unroll
            for (int o = 16; o; o >>= 1) ssum += __shfl_xor_sync(0xffffffffu, ssum, o);
        }
        inv = 1.0f / (ssum + 1e-8f);
    } else {
        // generic: smem candidates (broadcast LDS) or full row from global
        const float* cb = useSmem ? cand : (logits + (size_t)row * NCOLS);
        const float  sc = useSmem ? 1.0f : 0.5f;
        const int    n  = useSmem ? cn : NCOLS;

        float gfin = 0.f;
        for (int it = 0; it < 24; ++it) {
            float g = 0.f, gp = 0.f;
            for (int i = lane; i < n; i += 32) {
                float d = sc * cb[i] - tau;
                if (d > 0.f) { g = fmaf(d, d, g); gp += d; }
            }
            #pragma unroll
            for (int o = 16; o; o >>= 1) {
                g  += __shfl_xor_sync(0xffffffffu, g,  o);
                gp += __shfl_xor_sync(0xffffffffu, gp, o);
            }
            gfin = g;
            g -= 1.0f;
            if (gp <= 0.f) break;
            float step = g / (2.0f * gp);
            tau += step;
            if (step < 1e-7f) break;
        }
        int S = 0;
        for (int i = lane; i < n; i += 32) S += (sc * cb[i] > tau) ? 1 : 0;
        #pragma unroll
        for (int o = 16; o; o >>= 1) S += __shfl_xor_sync(0xffffffffu, S, o);

        th = tau;
        float ssum = gfin;
        if (S > KSEL) {
            useGe = 1;
            float lo = tau, hi = zmax;
            for (int it = 0; it < 48; ++it) {
                float mid = 0.5f * (lo + hi);
                int c = 0;
                for (int i = lane; i < n; i += 32) c += (sc * cb[i] >= mid) ? 1 : 0;
                #pragma unroll
                for (int o = 16; o; o >>= 1) c += __shfl_xor_sync(0xffffffffu, c, o);
                if (c >= KSEL) lo = mid; else hi = mid;
            }
            th = lo;
            ssum = 0.f;
            for (int i = lane; i < n; i += 32) {
                float z = sc * cb[i], d = z - tau;
                if (z >= th && d > 0.f) ssum = fmaf(d, d, ssum);
            }
            #pragma unroll
            for (int o = 16; o; o >>= 1) ssum += __shfl_xor_sync(0xffffffffu, ssum, o);
        }
        inv = 1.0f / (ssum + 1e-8f);
    }
    // no barrier: every warp holds identical tau/th/useGe/inv

    // ---------- Pass C: re-read (L2 hit), write weights (streaming), count ----------
    int sel = 0;
    #pragma unroll
    for (int j = 0; j < V4; ++j) {
        float4 v = src[tid + j * NT];
        float4 w;
        {
            float z = 0.5f * v.x, d = z - tau;
            bool keep = useGe ? (z >= th && d > 0.f) : (d > 0.f);
            w.x = keep ? d * d * inv : 0.f; sel += (w.x > 1e-6f);
        }
        {
            float z = 0.5f * v.y, d = z - tau;
            bool keep = useGe ? (z >= th && d > 0.f) : (d > 0.f);
            w.y = keep ? d * d * inv : 0.f; sel += (w.y > 1e-6f);
        }
        {
            float z = 0.5f * v.z, d = z - tau;
            bool keep = useGe ? (z >= th && d > 0.f) : (d > 0.f);
            w.z = keep ? d * d * inv : 0.f; sel += (w.z > 1e-6f);
        }
        {
            float z = 0.5f * v.w, d = z - tau;
            bool keep = useGe ? (z >= th && d > 0.f) : (d > 0.f);
            w.w = keep ? d * d * inv : 0.f; sel += (w.w > 1e-6f);
        }
        __stcs(&dst[tid + j * NT], w);           // evict-first: don't thrash L2
    }
    #pragma unroll
    for (int o = 16; o; o >>= 1) sel += __shfl_xor_sync(0xffffffffu, sel, o);
    if (lane == 0) s_i[wid] = sel;
    __syncthreads();
    if (tid == 0) {
        int t = 0;
        #pragma unroll
        for (int w = 0; w < NW; ++w) t += s_i[w];
        out_cnt[row] = (float)t;
    }
}

extern "C" void kernel_launch(void* const* d_in, const int* in_sizes, int n_in,
                              void* d_out, int out_size)
{
    const float* logits = (const float*)d_in[0];
    float* out = (float*)d_out;
    const int B = in_sizes[0] / NCOLS;
    entmax_topk_kernel<<<B, NT>>>(logits, out, out + (size_t)B * NCOLS);
}

// round 4
// speedup vs baseline: 1.1034x; 1.1034x over previous
#include <cuda_runtime.h>
#include <math.h>

#define NCOLS  16384
#define NT     512
#define V4     (NCOLS / 4 / NT)     // 8 float4 per thread (32 floats, in regs)
#define KSEL   256
#define CAP    4096
#define NW     (NT / 32)

// All-warps redundant tau solve over a candidate buffer (generic pointer:
// smem broadcast in the common case, global row in the adversarial fallback).
// Every warp executes identical ops on identical data -> identical results.
__device__ __forceinline__ void solve_tau(const float* __restrict__ buf, int n,
                                          float scale, float cutoff, float zmax,
                                          int lane,
                                          float& tau_o, float& th_o,
                                          float& inv_o, int& useGe_o)
{
    float tau = cutoff;
    float gfin = 0.f;
    for (int it = 0; it < 24; ++it) {
        float g = 0.f, gp = 0.f;
        for (int i = lane; i < n; i += 32) {
            float d = scale * buf[i] - tau;
            if (d > 0.f) { g = fmaf(d, d, g); gp += d; }
        }
        #pragma unroll
        for (int o = 16; o; o >>= 1) {
            g  += __shfl_xor_sync(0xffffffffu, g,  o);
            gp += __shfl_xor_sync(0xffffffffu, gp, o);
        }
        gfin = g;
        g -= 1.0f;
        if (gp <= 0.f) break;
        float step = g / (2.0f * gp);
        tau += step;
        if (step < 1e-7f) break;
    }
    int S = 0;
    for (int i = lane; i < n; i += 32) S += (scale * buf[i] > tau) ? 1 : 0;
    #pragma unroll
    for (int o = 16; o; o >>= 1) S += __shfl_xor_sync(0xffffffffu, S, o);

    float th = tau;
    int useGe = 0;
    float ssum = gfin;                      // sum (z-tau)_+^2 at final tau
    if (S > KSEL) {                         // rare: bisect K-th largest z
        useGe = 1;
        float lo = tau, hi = zmax;
        for (int it = 0; it < 48; ++it) {
            float mid = 0.5f * (lo + hi);
            int c = 0;
            for (int i = lane; i < n; i += 32) c += (scale * buf[i] >= mid) ? 1 : 0;
            #pragma unroll
            for (int o = 16; o; o >>= 1) c += __shfl_xor_sync(0xffffffffu, c, o);
            if (c >= KSEL) lo = mid; else hi = mid;
        }
        th = lo;
        ssum = 0.f;
        for (int i = lane; i < n; i += 32) {
            float z = scale * buf[i], d = z - tau;
            if (z >= th && d > 0.f) ssum = fmaf(d, d, ssum);
        }
        #pragma unroll
        for (int o = 16; o; o >>= 1) ssum += __shfl_xor_sync(0xffffffffu, ssum, o);
    }
    tau_o = tau; th_o = th; useGe_o = useGe;
    inv_o = 1.0f / (ssum + 1e-8f);
}

__global__ __launch_bounds__(NT, 2)
void entmax_topk_kernel(const float* __restrict__ logits,
                        float* __restrict__ out_w,
                        float* __restrict__ out_cnt)
{
    __shared__ float cand[CAP];
    __shared__ float s_f[NW];
    __shared__ int   s_i[NW];
    __shared__ int   s_cn;

    const int tid  = threadIdx.x;
    const int lane = tid & 31;
    const int wid  = tid >> 5;
    const int row  = blockIdx.x;

    const float4* src = reinterpret_cast<const float4*>(logits) + (size_t)row * (NCOLS / 4);
    float4*       dst = reinterpret_cast<float4*>(out_w)        + (size_t)row * (NCOLS / 4);

    // ---------- Pass A: single DRAM read (evict-first), row lives in regs ----------
    float4 v[V4];
    float lmax = -INFINITY;
    #pragma unroll
    for (int j = 0; j < V4; ++j) {
        float4 t = __ldcs(&src[tid + j * NT]);
        t.x *= 0.5f; t.y *= 0.5f; t.z *= 0.5f; t.w *= 0.5f;   // z = 0.5 * logit
        v[j] = t;
        lmax = fmaxf(lmax, fmaxf(fmaxf(t.x, t.y), fmaxf(t.z, t.w)));
    }
    #pragma unroll
    for (int o = 16; o; o >>= 1) lmax = fmaxf(lmax, __shfl_xor_sync(0xffffffffu, lmax, o));
    if (lane == 0) s_f[wid] = lmax;
    __syncthreads();
    if (wid == 0) {
        float m = (lane < NW) ? s_f[lane] : -INFINITY;
        #pragma unroll
        for (int o = 16; o; o >>= 1) m = fmaxf(m, __shfl_xor_sync(0xffffffffu, m, o));
        if (lane == 0) s_f[0] = m;
    }
    __syncthreads();
    const float zmax   = s_f[0];
    const float cutoff = zmax - 1.0f;       // rigorous lower bound on tau
    __syncthreads();                         // guard s_f reuse

    // ---------- Compaction: candidates z > cutoff, straight from regs ----------
    int lc = 0;
    #pragma unroll
    for (int j = 0; j < V4; ++j) {
        lc += (v[j].x > cutoff) + (v[j].y > cutoff)
            + (v[j].z > cutoff) + (v[j].w > cutoff);
    }
    int inc = lc;
    #pragma unroll
    for (int o = 1; o < 32; o <<= 1) {
        int t = __shfl_up_sync(0xffffffffu, inc, o);
        if (lane >= o) inc += t;
    }
    if (lane == 31) s_i[wid] = inc;
    __syncthreads();
    if (wid == 0) {
        int a = (lane < NW) ? s_i[lane] : 0;
        int winc = a;
        #pragma unroll
        for (int o = 1; o < NW; o <<= 1) {
            int u = __shfl_up_sync(0xffffffffu, winc, o);
            if (lane >= o) winc += u;
        }
        if (lane < NW) s_i[lane] = winc - a;   // exclusive warp bases
        if (lane == NW - 1) s_cn = winc;
    }
    __syncthreads();
    const int  cn      = s_cn;                 // >= 1 always (zmax itself)
    const bool useSmem = (cn <= CAP);
    if (useSmem && lc > 0) {
        int o = s_i[wid] + (inc - lc);
        #pragma unroll
        for (int j = 0; j < V4; ++j) {
            if (v[j].x > cutoff) cand[o++] = v[j].x;
            if (v[j].y > cutoff) cand[o++] = v[j].y;
            if (v[j].z > cutoff) cand[o++] = v[j].z;
            if (v[j].w > cutoff) cand[o++] = v[j].w;
        }
    }
    __syncthreads();

    // ---------- tau solve: all warps redundantly (no broadcast barrier needed) ----------
    float tau, th, inv;
    int useGe;
    if (useSmem) {
        solve_tau(cand, cn, 1.0f, cutoff, zmax, lane, tau, th, inv, useGe);
    } else {   // adversarial fallback: candidates exceed CAP -> scan full row
        solve_tau(logits + (size_t)row * NCOLS, NCOLS, 0.5f, cutoff, zmax, lane,
                  tau, th, inv, useGe);
    }

    // ---------- Output: straight from regs, streaming stores ----------
    int sel = 0;
    #pragma unroll
    for (int j = 0; j < V4; ++j) {
        float4 w;
        {
            float z = v[j].x, d = z - tau;
            bool keep = useGe ? (z >= th && d > 0.f) : (d > 0.f);
            w.x = keep ? d * d * inv : 0.f; sel += (w.x > 1e-6f);
        }
        {
            float z = v[j].y, d = z - tau;
            bool keep = useGe ? (z >= th && d > 0.f) : (d > 0.f);
            w.y = keep ? d * d * inv : 0.f; sel += (w.y > 1e-6f);
        }
        {
            float z = v[j].z, d = z - tau;
            bool keep = useGe ? (z >= th && d > 0.f) : (d > 0.f);
            w.z = keep ? d * d * inv : 0.f; sel += (w.z > 1e-6f);
        }
        {
            float z = v[j].w, d = z - tau;
            bool keep = useGe ? (z >= th && d > 0.f) : (d > 0.f);
            w.w = keep ? d * d * inv : 0.f; sel += (w.w > 1e-6f);
        }
        __stcs(&dst[tid + j * NT], w);
    }
    #pragma unroll
    for (int o = 16; o; o >>= 1) sel += __shfl_xor_sync(0xffffffffu, sel, o);
    if (lane == 0) s_i[wid] = sel;
    __syncthreads();
    if (tid == 0) {
        int t = 0;
        #pragma unroll
        for (int w = 0; w < NW; ++w) t += s_i[w];
        out_cnt[row] = (float)t;
    }
}

extern "C" void kernel_launch(void* const* d_in, const int* in_sizes, int n_in,
                              void* d_out, int out_size)
{
    const float* logits = (const float*)d_in[0];
    float* out = (float*)d_out;
    const int B = in_sizes[0] / NCOLS;
    entmax_topk_kernel<<<B, NT>>>(logits, out, out + (size_t)B * NCOLS);
}

// round 5
// speedup vs baseline: 1.3490x; 1.2226x over previous
#include <cuda_runtime.h>
#include <math.h>

#define NCOLS  16384
#define NT     512
#define V4     (NCOLS / 4 / NT)     // 8 float4 per thread (32 floats, in regs)
#define KSEL   256
#define CAP    4096
#define NW     (NT / 32)

__global__ __launch_bounds__(NT, 2)
void entmax_topk_kernel(const float* __restrict__ logits,
                        float* __restrict__ out_w,
                        float* __restrict__ out_cnt)
{
    __shared__ float cand[CAP];
    __shared__ float s_f[NW];
    __shared__ int   s_i[NW];
    __shared__ float s_tau, s_th, s_inv;
    __shared__ int   s_useGe;

    const int tid  = threadIdx.x;
    const int lane = tid & 31;
    const int wid  = tid >> 5;
    const int row  = blockIdx.x;

    const float4* src = reinterpret_cast<const float4*>(logits) + (size_t)row * (NCOLS / 4);
    float4*       dst = reinterpret_cast<float4*>(out_w)        + (size_t)row * (NCOLS / 4);

    // ---------- Pass A: single DRAM read (evict-first), row lives in regs ----------
    float4 v[V4];
    float lmax = -INFINITY;
    #pragma unroll
    for (int j = 0; j < V4; ++j) {
        float4 t = __ldcs(&src[tid + j * NT]);
        t.x *= 0.5f; t.y *= 0.5f; t.z *= 0.5f; t.w *= 0.5f;   // z = 0.5 * logit
        v[j] = t;
        lmax = fmaxf(lmax, fmaxf(fmaxf(t.x, t.y), fmaxf(t.z, t.w)));
    }
    #pragma unroll
    for (int o = 16; o; o >>= 1) lmax = fmaxf(lmax, __shfl_xor_sync(0xffffffffu, lmax, o));
    if (lane == 0) s_f[wid] = lmax;
    __syncthreads();                                   // barrier 1
    // every warp combines the 16 warp-maxes itself (tiny; saves a barrier)
    {
        float m = (lane < NW) ? s_f[lane] : -INFINITY;
        #pragma unroll
        for (int o = 8; o; o >>= 1) m = fmaxf(m, __shfl_xor_sync(0xffffffffu, m, o));
        lmax = __shfl_sync(0xffffffffu, m, 0);
    }
    const float zmax   = lmax;
    const float cutoff = zmax - 1.0f;                  // rigorous lower bound on tau

    // ---------- Compaction: candidates z > cutoff, straight from regs ----------
    int lc = 0;
    #pragma unroll
    for (int j = 0; j < V4; ++j) {
        lc += (v[j].x > cutoff) + (v[j].y > cutoff)
            + (v[j].z > cutoff) + (v[j].w > cutoff);
    }
    int inc = lc;
    #pragma unroll
    for (int o = 1; o < 32; o <<= 1) {
        int t = __shfl_up_sync(0xffffffffu, inc, o);
        if (lane >= o) inc += t;
    }
    if (lane == 31) s_i[wid] = inc;
    __syncthreads();                                   // barrier 2
    // every warp computes its own exclusive base + total from the 16 warp sums
    int wbase, cn;
    {
        int a = (lane < NW) ? s_i[lane] : 0;
        int sc = a;
        #pragma unroll
        for (int o = 1; o < NW; o <<= 1) {
            int u = __shfl_up_sync(0xffffffffu, sc, o);
            if (lane >= o) sc += u;
        }
        cn    = __shfl_sync(0xffffffffu, sc, NW - 1);         // total candidates
        wbase = __shfl_sync(0xffffffffu, sc - a, wid);        // exclusive base of my warp
    }
    const bool useSmem = (cn <= CAP);
    if (useSmem && lc > 0) {
        int o = wbase + (inc - lc);
        #pragma unroll
        for (int j = 0; j < V4; ++j) {
            if (v[j].x > cutoff) cand[o++] = v[j].x;
            if (v[j].y > cutoff) cand[o++] = v[j].y;
            if (v[j].z > cutoff) cand[o++] = v[j].z;
            if (v[j].w > cutoff) cand[o++] = v[j].w;
        }
    }
    __syncthreads();                                   // barrier 3

    // ---------- tau solve: WARP 0 ONLY (others wait -> no issue pressure) ----------
    if (wid == 0) {
        float tau = cutoff, th, inv;
        int useGe = 0;

        if (useSmem && cn <= 256) {
            // register-cached fast path (typical cn ~ 175)
            float rv[8];
            #pragma unroll
            for (int r = 0; r < 8; ++r) {
                int idx = r * 32 + lane;
                rv[r] = (idx < cn) ? cand[idx] : -1e30f;
            }
            float gfin = 0.f;
            for (int it = 0; it < 24; ++it) {
                float g = 0.f, gp = 0.f;
                #pragma unroll
                for (int r = 0; r < 8; ++r) {
                    float d = rv[r] - tau;
                    if (d > 0.f) { g = fmaf(d, d, g); gp += d; }
                }
                #pragma unroll
                for (int o = 16; o; o >>= 1) {
                    g  += __shfl_xor_sync(0xffffffffu, g,  o);
                    gp += __shfl_xor_sync(0xffffffffu, gp, o);
                }
                gfin = g;
                g -= 1.0f;
                if (gp <= 0.f) break;
                float step = g / (2.0f * gp);
                tau += step;
                if (step < 1e-7f) break;
            }
            int S = 0;
            #pragma unroll
            for (int r = 0; r < 8; ++r) S += (rv[r] > tau) ? 1 : 0;
            #pragma unroll
            for (int o = 16; o; o >>= 1) S += __shfl_xor_sync(0xffffffffu, S, o);

            th = tau;
            float ssum = gfin;                   // sum (z-tau)_+^2 at final tau
            if (S > KSEL) {                      // rare: bisect K-th largest z
                useGe = 1;
                float lo = tau, hi = zmax;
                for (int it = 0; it < 48; ++it) {
                    float mid = 0.5f * (lo + hi);
                    int c = 0;
                    #pragma unroll
                    for (int r = 0; r < 8; ++r) c += (rv[r] >= mid) ? 1 : 0;
                    #pragma unroll
                    for (int o = 16; o; o >>= 1) c += __shfl_xor_sync(0xffffffffu, c, o);
                    if (c >= KSEL) lo = mid; else hi = mid;
                }
                th = lo;
                ssum = 0.f;
                #pragma unroll
                for (int r = 0; r < 8; ++r) {
                    float z = rv[r], d = z - tau;
                    if (z >= th && d > 0.f) ssum = fmaf(d, d, ssum);
                }
                #pragma unroll
                for (int o = 16; o; o >>= 1) ssum += __shfl_xor_sync(0xffffffffu, ssum, o);
            }
            inv = 1.0f / (ssum + 1e-8f);
        } else {
            // generic path: smem candidates, or full row from global (adversarial)
            const float* cb = useSmem ? cand : (logits + (size_t)row * NCOLS);
            const float  sc = useSmem ? 1.0f : 0.5f;
            const int    n  = useSmem ? cn : NCOLS;

            float gfin = 0.f;
            for (int it = 0; it < 24; ++it) {
                float g = 0.f, gp = 0.f;
                for (int i = lane; i < n; i += 32) {
                    float d = sc * cb[i] - tau;
                    if (d > 0.f) { g = fmaf(d, d, g); gp += d; }
                }
                #pragma unroll
                for (int o = 16; o; o >>= 1) {
                    g  += __shfl_xor_sync(0xffffffffu, g,  o);
                    gp += __shfl_xor_sync(0xffffffffu, gp, o);
                }
                gfin = g;
                g -= 1.0f;
                if (gp <= 0.f) break;
                float step = g / (2.0f * gp);
                tau += step;
                if (step < 1e-7f) break;
            }
            int S = 0;
            for (int i = lane; i < n; i += 32) S += (sc * cb[i] > tau) ? 1 : 0;
            #pragma unroll
            for (int o = 16; o; o >>= 1) S += __shfl_xor_sync(0xffffffffu, S, o);

            th = tau;
            float ssum = gfin;
            if (S > KSEL) {
                useGe = 1;
                float lo = tau, hi = zmax;
                for (int it = 0; it < 48; ++it) {
                    float mid = 0.5f * (lo + hi);
                    int c = 0;
                    for (int i = lane; i < n; i += 32) c += (sc * cb[i] >= mid) ? 1 : 0;
                    #pragma unroll
                    for (int o = 16; o; o >>= 1) c += __shfl_xor_sync(0xffffffffu, c, o);
                    if (c >= KSEL) lo = mid; else hi = mid;
                }
                th = lo;
                ssum = 0.f;
                for (int i = lane; i < n; i += 32) {
                    float z = sc * cb[i], d = z - tau;
                    if (z >= th && d > 0.f) ssum = fmaf(d, d, ssum);
                }
                #pragma unroll
                for (int o = 16; o; o >>= 1) ssum += __shfl_xor_sync(0xffffffffu, ssum, o);
            }
            inv = 1.0f / (ssum + 1e-8f);
        }

        if (lane == 0) { s_tau = tau; s_th = th; s_useGe = useGe; s_inv = inv; }
    }
    __syncthreads();                                   // barrier 4

    const float tau = s_tau, th = s_th, inv = s_inv;
    const int   useGe = s_useGe;

    // ---------- Output: straight from regs, streaming stores ----------
    int sel = 0;
    #pragma unroll
    for (int j = 0; j < V4; ++j) {
        float4 w;
        {
            float z = v[j].x, d = z - tau;
            bool keep = useGe ? (z >= th && d > 0.f) : (d > 0.f);
            w.x = keep ? d * d * inv : 0.f; sel += (w.x > 1e-6f);
        }
        {
            float z = v[j].y, d = z - tau;
            bool keep = useGe ? (z >= th && d > 0.f) : (d > 0.f);
            w.y = keep ? d * d * inv : 0.f; sel += (w.y > 1e-6f);
        }
        {
            float z = v[j].z, d = z - tau;
            bool keep = useGe ? (z >= th && d > 0.f) : (d > 0.f);
            w.z = keep ? d * d * inv : 0.f; sel += (w.z > 1e-6f);
        }
        {
            float z = v[j].w, d = z - tau;
            bool keep = useGe ? (z >= th && d > 0.f) : (d > 0.f);
            w.w = keep ? d * d * inv : 0.f; sel += (w.w > 1e-6f);
        }
        __stcs(&dst[tid + j * NT], w);
    }
    #pragma unroll
    for (int o = 16; o; o >>= 1) sel += __shfl_xor_sync(0xffffffffu, sel, o);
    if (lane == 0) s_i[wid] = sel;
    __syncthreads();
    if (tid == 0) {
        int t = 0;
        #pragma unroll
        for (int w = 0; w < NW; ++w) t += s_i[w];
        out_cnt[row] = (float)t;
    }
}

extern "C" void kernel_launch(void* const* d_in, const int* in_sizes, int n_in,
                              void* d_out, int out_size)
{
    const float* logits = (const float*)d_in[0];
    float* out = (float*)d_out;
    const int B = in_sizes[0] / NCOLS;
    entmax_topk_kernel<<<B, NT>>>(logits, out, out + (size_t)B * NCOLS);
}